// round 1
// baseline (speedup 1.0000x reference)
#include <cuda_runtime.h>

// Problem constants
#define NB    8
#define HH    64
#define WWID  64
#define CINCH 512
#define COUTC 512
#define ZDIM  512
#define M_TOT (NB * HH * WWID)      // 32768 output pixels

// GEMM tiling
#define BM 128
#define BN 64
#define BK 16

// sqrt(2/512) = 1/16 exactly; sqrt(2/(512*9)) = sqrt(1/2304) = 1/48 exactly
#define DENSE_COEF (0.0625f)
#define CONV_COEF  (1.0f / 48.0f)
#define CONV_COEF2 (1.0f / 2304.0f)

// Scratch (no allocations allowed in kernel_launch)
__device__ float g_s[NB * CINCH];        // style vector s[n, cin]
__device__ float g_d[NB * COUTC];        // demod d[n, cout]
__device__ float g_w2[CINCH * COUTC];    // sum_{taps} (w*coef)^2 [cin, cout]

// ---------------------------------------------------------------------------
// Kernel 1: s[n,c] = latent[n,:] @ dense_w[:,c] * DENSE_COEF + dense_b[c]
// grid = NB blocks, 512 threads
// ---------------------------------------------------------------------------
__global__ void k_style(const float* __restrict__ latent,
                        const float* __restrict__ dense_w,
                        const float* __restrict__ dense_b) {
    const int n = blockIdx.x;
    const int c = threadIdx.x;
    const float* lp = latent + n * ZDIM;
    float acc = 0.0f;
#pragma unroll 8
    for (int z = 0; z < ZDIM; ++z) {
        acc = fmaf(lp[z], dense_w[z * CINCH + c], acc);
    }
    g_s[n * CINCH + c] = acc * DENSE_COEF + dense_b[c];
}

// ---------------------------------------------------------------------------
// Kernel 2: w2[cin,cout] = sum_{tap} (conv_w[tap,cin,cout])^2 * CONV_COEF2
// grid = CIN*COUT/256 blocks, 256 threads
// ---------------------------------------------------------------------------
__global__ void k_w2(const float* __restrict__ conv_w) {
    const int i = blockIdx.x * 256 + threadIdx.x;   // cin*512 + cout
    float acc = 0.0f;
#pragma unroll
    for (int t = 0; t < 9; ++t) {
        float v = conv_w[t * (CINCH * COUTC) + i];
        acc = fmaf(v, v, acc);
    }
    g_w2[i] = acc * CONV_COEF2;
}

// ---------------------------------------------------------------------------
// Kernel 3: d[n,cout] = rsqrt( sum_cin s[n,cin]^2 * w2[cin,cout] + 1e-8 )
// grid = NB blocks, 512 threads
// ---------------------------------------------------------------------------
__global__ void k_demod() {
    __shared__ float s2[CINCH];
    const int n = blockIdx.x;
    const int c = threadIdx.x;
    float sv = g_s[n * CINCH + c];
    s2[c] = sv * sv;
    __syncthreads();
    float acc = 0.0f;
#pragma unroll 8
    for (int ci = 0; ci < CINCH; ++ci) {
        acc = fmaf(s2[ci], g_w2[ci * COUTC + c], acc);
    }
    g_d[n * COUTC + c] = rsqrtf(acc + 1e-8f);
}

// ---------------------------------------------------------------------------
// Kernel 4: fused modulated conv (implicit GEMM) + demod + bias + noise + leaky
//   C[m, cout] = sum_{tap, cin} data[n, h+dy, w+dx, cin] * s[n,cin]
//                               * conv_w[tap, cin, cout] * CONV_COEF
//   out = leaky(C * d[n,cout] + bias[cout] + noise * noise_coef[cout])
// grid = (M_TOT/BM, COUT/BN), 256 threads, 8x4 microtile per thread
// ---------------------------------------------------------------------------
__global__ void __launch_bounds__(256)
k_conv(const float* __restrict__ data,
       const float* __restrict__ conv_w,
       const float* __restrict__ bias,
       const float* __restrict__ ncoef,
       const float* __restrict__ noise,
       float* __restrict__ out) {
    __shared__ float As[BK][BM];
    __shared__ float Bs[BK][BN];

    const int tid = threadIdx.x;
    const int bm  = blockIdx.x * BM;     // pixel offset
    const int bn  = blockIdx.y * BN;     // cout offset
    const int n_img = bm >> 12;          // 4096 pixels per image; BM|4096 so constant per block

    // A staging indices: thread loads 8 consecutive cin (2x float4) for one pixel row
    const int a_m = tid >> 1;            // 0..127 (pixel within tile)
    const int a_k = (tid & 1) << 3;      // 0 or 8 (cin offset within BK)
    const int m_a = bm + a_m;
    const int h   = (m_a >> 6) & 63;
    const int w   = m_a & 63;

    // B staging indices: thread loads 4 consecutive couts for one k
    const int b_k = tid >> 4;            // 0..15
    const int b_c = (tid & 15) << 2;     // 0..60

    // compute mapping
    const int ty = tid >> 4;             // 0..15 -> 8 pixels each
    const int tx = tid & 15;             // 0..15 -> 4 couts each

    float acc[8][4];
#pragma unroll
    for (int i = 0; i < 8; ++i)
#pragma unroll
        for (int j = 0; j < 4; ++j) acc[i][j] = 0.0f;

    const float* s_ptr = g_s + n_img * CINCH + a_k;

    for (int tap = 0; tap < 9; ++tap) {
        const int dy = tap / 3 - 1;
        const int dx = tap - (tap / 3) * 3 - 1;
        const int hh = h + dy;
        const int ww = w + dx;
        const bool valid = ((unsigned)hh < 64u) && ((unsigned)ww < 64u);
        const float* a_ptr = data + ((size_t)((n_img * 64 + hh) * 64 + ww)) * CINCH + a_k;
        const float* b_ptr = conv_w + (size_t)tap * (CINCH * COUTC) + b_k * COUTC + bn + b_c;

        for (int c0 = 0; c0 < CINCH; c0 += BK) {
            float4 a0 = make_float4(0.f, 0.f, 0.f, 0.f);
            float4 a1 = a0;
            if (valid) {
                a0 = *(const float4*)(a_ptr + c0);
                a1 = *(const float4*)(a_ptr + c0 + 4);
            }
            const float4 s0 = *(const float4*)(s_ptr + c0);
            const float4 s1 = *(const float4*)(s_ptr + c0 + 4);
            const float4 bv = *(const float4*)(b_ptr + c0 * COUTC);

            As[a_k + 0][a_m] = a0.x * s0.x;
            As[a_k + 1][a_m] = a0.y * s0.y;
            As[a_k + 2][a_m] = a0.z * s0.z;
            As[a_k + 3][a_m] = a0.w * s0.w;
            As[a_k + 4][a_m] = a1.x * s1.x;
            As[a_k + 5][a_m] = a1.y * s1.y;
            As[a_k + 6][a_m] = a1.z * s1.z;
            As[a_k + 7][a_m] = a1.w * s1.w;

            *(float4*)&Bs[b_k][b_c] = make_float4(bv.x * CONV_COEF, bv.y * CONV_COEF,
                                                  bv.z * CONV_COEF, bv.w * CONV_COEF);
            __syncthreads();

#pragma unroll
            for (int k = 0; k < BK; ++k) {
                float a[8], b[4];
                *(float4*)(a)     = *(const float4*)&As[k][ty * 8];
                *(float4*)(a + 4) = *(const float4*)&As[k][ty * 8 + 4];
                *(float4*)(b)     = *(const float4*)&Bs[k][tx * 4];
#pragma unroll
                for (int i = 0; i < 8; ++i)
#pragma unroll
                    for (int j = 0; j < 4; ++j)
                        acc[i][j] = fmaf(a[i], b[j], acc[i][j]);
            }
            __syncthreads();
        }
    }

    // Epilogue: demod, bias, noise, leaky relu
    const int c_base = bn + tx * 4;
    const float4 dv  = *(const float4*)(g_d + n_img * COUTC + c_base);
    const float4 biv = *(const float4*)(bias + c_base);
    const float4 ncv = *(const float4*)(ncoef + c_base);

#pragma unroll
    for (int i = 0; i < 8; ++i) {
        const int mm = bm + ty * 8 + i;
        const float4 nz = *(const float4*)(noise + (size_t)mm * COUTC + c_base);
        float4 o;
        o.x = fmaf(acc[i][0], dv.x, fmaf(nz.x, ncv.x, biv.x));
        o.y = fmaf(acc[i][1], dv.y, fmaf(nz.y, ncv.y, biv.y));
        o.z = fmaf(acc[i][2], dv.z, fmaf(nz.z, ncv.z, biv.z));
        o.w = fmaf(acc[i][3], dv.w, fmaf(nz.w, ncv.w, biv.w));
        o.x = (o.x >= 0.f) ? o.x : 0.2f * o.x;
        o.y = (o.y >= 0.f) ? o.y : 0.2f * o.y;
        o.z = (o.z >= 0.f) ? o.z : 0.2f * o.z;
        o.w = (o.w >= 0.f) ? o.w : 0.2f * o.w;
        *(float4*)(out + (size_t)mm * COUTC + c_base) = o;
    }
}

// ---------------------------------------------------------------------------
// Launch
// ---------------------------------------------------------------------------
extern "C" void kernel_launch(void* const* d_in, const int* in_sizes, int n_in,
                              void* d_out, int out_size) {
    const float* data    = (const float*)d_in[0];   // [8,64,64,512]
    const float* latent  = (const float*)d_in[1];   // [8,512]
    const float* dense_w = (const float*)d_in[2];   // [512,512]
    const float* dense_b = (const float*)d_in[3];   // [512]
    const float* conv_w  = (const float*)d_in[4];   // [3,3,512,512]
    const float* bias    = (const float*)d_in[5];   // [512]
    const float* ncoef   = (const float*)d_in[6];   // [512]
    const float* noise   = (const float*)d_in[7];   // [8,64,64,512]
    float* out = (float*)d_out;

    k_style<<<NB, CINCH>>>(latent, dense_w, dense_b);
    k_w2<<<(CINCH * COUTC) / 256, 256>>>(conv_w);
    k_demod<<<NB, COUTC>>>();

    dim3 grid(M_TOT / BM, COUTC / BN);
    k_conv<<<grid, 256>>>(data, conv_w, bias, ncoef, noise, out);
}

// round 3
// speedup vs baseline: 3.2440x; 3.2440x over previous
#include <cuda_runtime.h>
#include <cstdint>

// ---------------------------------------------------------------------------
// Problem constants
// ---------------------------------------------------------------------------
#define NB    8
#define CINCH 512
#define COUTC 512
#define ZDIM  512
#define M_TOT (NB * 64 * 64)        // 32768 pixels
#define KTOT  (9 * CINCH)           // 4608

#define DENSE_COEF (0.0625f)        // sqrt(2/512)
#define CONV_COEF  (1.0f / 48.0f)   // sqrt(2/4608)
#define CONV_COEF2 (1.0f / 2304.0f)

// GEMM tiling
#define BM 128
#define BN 256
#define BK 32
#define NSTG_TOT (KTOT / BK)        // 144 k-stages
#define STAGES 3

// smem: rows padded to 36 floats (stride 144B) -> conflict-free frag loads
#define ROWP 36
#define A_ST_FLOATS (BM * ROWP)     // 4608 floats  (18432 B)
#define B_ST_FLOATS (BN * ROWP)     // 9216 floats  (36864 B)
#define STAGE_FLOATS (A_ST_FLOATS + B_ST_FLOATS)   // 13824 (55296 B)
#define SMEM_TOTAL (STAGES * STAGE_FLOATS * 4)     // 165888 B

// ---------------------------------------------------------------------------
// Scratch (device globals; no runtime allocation allowed)
// ---------------------------------------------------------------------------
__device__ float g_s[NB * CINCH];
__device__ float g_d[NB * COUTC];
__device__ float g_w2[CINCH * COUTC];
__device__ float g_X[M_TOT * CINCH];     // modulated input, tf32-rounded, [m][cin]
__device__ float g_Bt[COUTC * KTOT];     // weights K-major, tf32-rounded, [cout][tap*512+cin]

// ---------------------------------------------------------------------------
// Helpers
// ---------------------------------------------------------------------------
__device__ __forceinline__ uint32_t smem_u32(const void* p) {
    uint32_t a;
    asm("{ .reg .u64 t; cvta.to.shared.u64 t, %1; cvt.u32.u64 %0, t; }" : "=r"(a) : "l"(p));
    return a;
}

__device__ __forceinline__ float tf32_rna(float x) {
    uint32_t u;
    asm("cvt.rna.tf32.f32 %0, %1;" : "=r"(u) : "f"(x));
    return __uint_as_float(u);
}

__device__ __forceinline__ void cpa16(uint32_t dst, const float* src, uint32_t sz) {
    asm volatile("cp.async.cg.shared.global.L2::128B [%0], [%1], 16, %2;"
                 :: "r"(dst), "l"(src), "r"(sz) : "memory");
}

#define CP_COMMIT() asm volatile("cp.async.commit_group;" ::: "memory")
#define CP_WAIT1()  asm volatile("cp.async.wait_group 1;" ::: "memory")

#define MMA_TF32(d, a, b)                                                     \
    asm volatile(                                                             \
        "mma.sync.aligned.m16n8k8.row.col.f32.tf32.tf32.f32 "                 \
        "{%0,%1,%2,%3}, {%4,%5,%6,%7}, {%8,%9}, {%0,%1,%2,%3};"               \
        : "+f"((d)[0]), "+f"((d)[1]), "+f"((d)[2]), "+f"((d)[3])              \
        : "r"((a)[0]), "r"((a)[1]), "r"((a)[2]), "r"((a)[3]),                 \
          "r"((b)[0]), "r"((b)[1]))

// ---------------------------------------------------------------------------
// Prologue kernels
// ---------------------------------------------------------------------------
__global__ void k_style(const float* __restrict__ latent,
                        const float* __restrict__ dense_w,
                        const float* __restrict__ dense_b) {
    const int n = blockIdx.x;
    const int c = threadIdx.x;
    const float* lp = latent + n * ZDIM;
    float a0 = 0.f, a1 = 0.f, a2 = 0.f, a3 = 0.f;
#pragma unroll 4
    for (int z = 0; z < ZDIM; z += 4) {
        a0 = fmaf(lp[z + 0], dense_w[(z + 0) * CINCH + c], a0);
        a1 = fmaf(lp[z + 1], dense_w[(z + 1) * CINCH + c], a1);
        a2 = fmaf(lp[z + 2], dense_w[(z + 2) * CINCH + c], a2);
        a3 = fmaf(lp[z + 3], dense_w[(z + 3) * CINCH + c], a3);
    }
    g_s[n * CINCH + c] = (a0 + a1 + a2 + a3) * DENSE_COEF + dense_b[c];
}

__global__ void k_w2(const float* __restrict__ conv_w) {
    const int i = blockIdx.x * 256 + threadIdx.x;
    float acc = 0.0f;
#pragma unroll
    for (int t = 0; t < 9; ++t) {
        float v = conv_w[t * (CINCH * COUTC) + i];
        acc = fmaf(v, v, acc);
    }
    g_w2[i] = acc * CONV_COEF2;
}

__global__ void k_demod() {
    __shared__ float s2[CINCH];
    const int n = blockIdx.x;
    const int c = threadIdx.x;
    float sv = g_s[n * CINCH + c];
    s2[c] = sv * sv;
    __syncthreads();
    float acc = 0.0f;
#pragma unroll 8
    for (int ci = 0; ci < CINCH; ++ci)
        acc = fmaf(s2[ci], g_w2[ci * COUTC + c], acc);
    g_d[n * COUTC + c] = rsqrtf(acc + 1e-8f);
}

// X = rna_tf32(data * s)
__global__ void k_mod(const float* __restrict__ data) {
    const int e4 = blockIdx.x * 256 + threadIdx.x;
    const float4 v = ((const float4*)data)[e4];
    const int m = e4 >> 7;
    const int n = m >> 12;
    const int c = (e4 & 127) << 2;
    const float4 sv = *(const float4*)(g_s + n * CINCH + c);
    float4 o;
    o.x = tf32_rna(v.x * sv.x);
    o.y = tf32_rna(v.y * sv.y);
    o.z = tf32_rna(v.z * sv.z);
    o.w = tf32_rna(v.w * sv.w);
    ((float4*)g_X)[e4] = o;
}

// Bt[cout][tap*512+cin] = rna_tf32(conv_w[tap][cin][cout] * CONV_COEF)
__global__ void k_transb(const float* __restrict__ conv_w) {
    __shared__ float t[32][33];
    const int cout0 = blockIdx.x * 32;
    const int cin0  = blockIdx.y * 32;
    const int tap   = blockIdx.z;
    const int tx = threadIdx.x;   // 0..31
    const int ty = threadIdx.y;   // 0..7
#pragma unroll
    for (int i = 0; i < 4; ++i) {
        int ci = ty + i * 8;
        float v = conv_w[((size_t)tap * CINCH + cin0 + ci) * COUTC + cout0 + tx];
        t[ci][tx] = tf32_rna(v * CONV_COEF);
    }
    __syncthreads();
#pragma unroll
    for (int i = 0; i < 4; ++i) {
        int co = ty + i * 8;
        g_Bt[(size_t)(cout0 + co) * KTOT + tap * CINCH + cin0 + tx] = t[tx][co];
    }
}

// ---------------------------------------------------------------------------
// Staging: load k-stage s (tap, cin-chunk) into smem buffers via cp.async
// ---------------------------------------------------------------------------
__device__ __forceinline__ void stage_load(uint32_t sA, uint32_t sB, int s,
                                           int tid, int n_img, int h0, int bn) {
    const int tap  = s >> 4;
    const int cin0 = (s & 15) * BK;
    const int dy = tap / 3 - 1;
    const int dx = tap % 3 - 1;

    // A: 128 rows x 8 chunks of 16B (consecutive tids -> consecutive chunks)
#pragma unroll
    for (int i = 0; i < 4; ++i) {
        const int c  = tid + 256 * i;
        const int m  = c >> 3;
        const int ch = c & 7;
        const int h = h0 + (m >> 6) + dy;
        const int w = (m & 63) + dx;
        const bool v = ((unsigned)h < 64u) && ((unsigned)w < 64u);
        const int hc = v ? h : 0;
        const int wc = v ? w : 0;
        const float* src = g_X + ((size_t)((n_img * 64 + hc) * 64 + wc)) * CINCH
                               + cin0 + ch * 4;
        cpa16(sA + m * (ROWP * 4) + ch * 16, src, v ? 16u : 0u);
    }
    // B: 256 rows x 8 chunks of 16B
#pragma unroll
    for (int i = 0; i < 8; ++i) {
        const int c  = tid + 256 * i;
        const int n  = c >> 3;
        const int ch = c & 7;
        const float* src = g_Bt + (size_t)(bn + n) * KTOT + tap * CINCH + cin0 + ch * 4;
        cpa16(sB + n * (ROWP * 4) + ch * 16, src, 16u);
    }
}

// ---------------------------------------------------------------------------
// Main kernel: tf32 mma.sync implicit GEMM + fused epilogue
// grid = (M_TOT/BM = 256, COUT/BN = 2), block = 256
// ---------------------------------------------------------------------------
__global__ void __launch_bounds__(256, 1)
k_conv_mma(const float* __restrict__ bias,
           const float* __restrict__ ncoef,
           const float* __restrict__ noise,
           float* __restrict__ out) {
    extern __shared__ float sm[];
    const uint32_t sbase = smem_u32(sm);

    const int tid  = threadIdx.x;
    const int wid  = tid >> 5;
    const int lane = tid & 31;
    const int gid  = lane >> 2;    // 0..7
    const int tid4 = lane & 3;     // 0..3
    const int wm = (wid >> 2) * 64;    // warp m-offset (0 or 64)
    const int wn = (wid & 3) * 64;     // warp n-offset (0,64,128,192)

    const int bm    = blockIdx.x * BM;
    const int bn    = blockIdx.y * BN;
    const int n_img = bm >> 12;
    const int h0    = (bm >> 6) & 63;

    float acc[4][8][4];
#pragma unroll
    for (int i = 0; i < 4; ++i)
#pragma unroll
        for (int j = 0; j < 8; ++j)
#pragma unroll
            for (int r = 0; r < 4; ++r) acc[i][j][r] = 0.0f;

    uint32_t sA[STAGES], sB[STAGES];
#pragma unroll
    for (int st = 0; st < STAGES; ++st) {
        sA[st] = sbase + st * (STAGE_FLOATS * 4);
        sB[st] = sA[st] + A_ST_FLOATS * 4;
    }

    // prologue: fill stages 0,1
    stage_load(sA[0], sB[0], 0, tid, n_img, h0, bn);
    CP_COMMIT();
    stage_load(sA[1], sB[1], 1, tid, n_img, h0, bn);
    CP_COMMIT();

    int buf = 0, nbuf = 2;
    for (int s = 0; s < NSTG_TOT; ++s) {
        CP_WAIT1();
        __syncthreads();

        if (s + 2 < NSTG_TOT)
            stage_load(sA[nbuf], sB[nbuf], s + 2, tid, n_img, h0, bn);
        CP_COMMIT();

        const float* As = sm + buf * STAGE_FLOATS;
        const float* Bs = As + A_ST_FLOATS;

#pragma unroll
        for (int kk = 0; kk < 4; ++kk) {
            const int k0 = kk * 8 + tid4;
            uint32_t a[4][4];
#pragma unroll
            for (int i = 0; i < 4; ++i) {
                const int r0 = wm + i * 16 + gid;
                a[i][0] = __float_as_uint(As[r0 * ROWP + k0]);
                a[i][1] = __float_as_uint(As[(r0 + 8) * ROWP + k0]);
                a[i][2] = __float_as_uint(As[r0 * ROWP + k0 + 4]);
                a[i][3] = __float_as_uint(As[(r0 + 8) * ROWP + k0 + 4]);
            }
            uint32_t b[8][2];
#pragma unroll
            for (int j = 0; j < 8; ++j) {
                const int nrow = wn + j * 8 + gid;
                b[j][0] = __float_as_uint(Bs[nrow * ROWP + k0]);
                b[j][1] = __float_as_uint(Bs[nrow * ROWP + k0 + 4]);
            }
#pragma unroll
            for (int i = 0; i < 4; ++i)
#pragma unroll
                for (int j = 0; j < 8; ++j)
                    MMA_TF32(acc[i][j], a[i], b[j]);
        }

        buf  = (buf == STAGES - 1) ? 0 : buf + 1;
        nbuf = (nbuf == STAGES - 1) ? 0 : nbuf + 1;
    }

    // ---------------- fused epilogue ----------------
    const float* d_row = g_d + n_img * COUTC;
#pragma unroll
    for (int j = 0; j < 8; ++j) {
        const int col = bn + wn + j * 8 + 2 * tid4;
        const float2 dv = *(const float2*)(d_row + col);
        const float2 bv = *(const float2*)(bias + col);
        const float2 cv = *(const float2*)(ncoef + col);
#pragma unroll
        for (int i = 0; i < 4; ++i) {
            const int r0 = bm + wm + i * 16 + gid;
#pragma unroll
            for (int half = 0; half < 2; ++half) {
                const int rr = r0 + half * 8;
                const float2 nz = *(const float2*)(noise + (size_t)rr * COUTC + col);
                float2 o;
                o.x = fmaf(acc[i][j][half * 2 + 0], dv.x, fmaf(nz.x, cv.x, bv.x));
                o.y = fmaf(acc[i][j][half * 2 + 1], dv.y, fmaf(nz.y, cv.y, bv.y));
                o.x = (o.x >= 0.f) ? o.x : 0.2f * o.x;
                o.y = (o.y >= 0.f) ? o.y : 0.2f * o.y;
                *(float2*)(out + (size_t)rr * COUTC + col) = o;
            }
        }
    }
}

// ---------------------------------------------------------------------------
// Launch
// ---------------------------------------------------------------------------
extern "C" void kernel_launch(void* const* d_in, const int* in_sizes, int n_in,
                              void* d_out, int out_size) {
    const float* data    = (const float*)d_in[0];
    const float* latent  = (const float*)d_in[1];
    const float* dense_w = (const float*)d_in[2];
    const float* dense_b = (const float*)d_in[3];
    const float* conv_w  = (const float*)d_in[4];
    const float* bias    = (const float*)d_in[5];
    const float* ncoef   = (const float*)d_in[6];
    const float* noise   = (const float*)d_in[7];
    float* out = (float*)d_out;

    static bool attr_set = false;
    if (!attr_set) {
        cudaFuncSetAttribute(k_conv_mma, cudaFuncAttributeMaxDynamicSharedMemorySize,
                             SMEM_TOTAL);
        attr_set = true;
    }

    k_style<<<NB, CINCH>>>(latent, dense_w, dense_b);
    k_w2<<<(CINCH * COUTC) / 256, 256>>>(conv_w);
    k_demod<<<NB, COUTC>>>();
    k_mod<<<(M_TOT * CINCH / 4) / 256, 256>>>(data);
    k_transb<<<dim3(COUTC / 32, CINCH / 32, 9), dim3(32, 8)>>>(conv_w);

    dim3 grid(M_TOT / BM, COUTC / BN);
    k_conv_mma<<<grid, 256, SMEM_TOTAL>>>(bias, ncoef, noise, out);
}

// round 4
// speedup vs baseline: 4.9833x; 1.5361x over previous
#include <cuda_runtime.h>
#include <cuda_fp16.h>
#include <cstdint>

// ---------------------------------------------------------------------------
// Problem constants
// ---------------------------------------------------------------------------
#define NB    8
#define CINCH 512
#define COUTC 512
#define ZDIM  512
#define M_TOT (NB * 64 * 64)        // 32768 pixels
#define KTOT  (9 * CINCH)           // 4608

#define DENSE_COEF (0.0625f)        // sqrt(2/512)
#define CONV_COEF  (1.0f / 48.0f)   // sqrt(2/4608)
#define CONV_COEF2 (1.0f / 2304.0f)

// GEMM tiling
#define BM 128
#define BN 256
#define BK 32
#define NSTG_TOT (KTOT / BK)        // 144 k-stages
#define STAGES 4

// smem rows: 32 halves (64B data) padded to 80B -> conflict-free ldmatrix
#define ROWB 80
#define A_ST_BYTES (BM * ROWB)      // 10240
#define B_ST_BYTES (BN * ROWB)      // 20480
#define STAGE_BYTES (A_ST_BYTES + B_ST_BYTES)   // 30720
#define SMEM_TOTAL (STAGES * STAGE_BYTES)       // 122880

// ---------------------------------------------------------------------------
// Scratch (device globals; no runtime allocation allowed)
// ---------------------------------------------------------------------------
__device__ float  g_s[NB * CINCH];
__device__ float  g_d[NB * COUTC];
__device__ float  g_w2[CINCH * COUTC];
__device__ __half g_X[M_TOT * CINCH];     // modulated input fp16, [m][cin]
__device__ __half g_Bt[COUTC * KTOT];     // weights fp16 K-major, [cout][tap*512+cin]

// ---------------------------------------------------------------------------
// Helpers
// ---------------------------------------------------------------------------
__device__ __forceinline__ uint32_t smem_u32(const void* p) {
    uint32_t a;
    asm("{ .reg .u64 t; cvta.to.shared.u64 t, %1; cvt.u32.u64 %0, t; }" : "=r"(a) : "l"(p));
    return a;
}

__device__ __forceinline__ void cpa16(uint32_t dst, const void* src, uint32_t sz) {
    asm volatile("cp.async.cg.shared.global.L2::128B [%0], [%1], 16, %2;"
                 :: "r"(dst), "l"(src), "r"(sz) : "memory");
}

#define CP_COMMIT() asm volatile("cp.async.commit_group;" ::: "memory")
#define CP_WAIT2()  asm volatile("cp.async.wait_group 2;" ::: "memory")

#define LDMX4(r, addr)                                                        \
    asm volatile("ldmatrix.sync.aligned.m8n8.x4.shared.b16 {%0,%1,%2,%3}, [%4];" \
                 : "=r"((r)[0]), "=r"((r)[1]), "=r"((r)[2]), "=r"((r)[3])     \
                 : "r"(addr))

#define MMA_F16(d, a, b0, b1)                                                 \
    asm volatile(                                                             \
        "mma.sync.aligned.m16n8k16.row.col.f32.f16.f16.f32 "                  \
        "{%0,%1,%2,%3}, {%4,%5,%6,%7}, {%8,%9}, {%0,%1,%2,%3};"               \
        : "+f"((d)[0]), "+f"((d)[1]), "+f"((d)[2]), "+f"((d)[3])              \
        : "r"((a)[0]), "r"((a)[1]), "r"((a)[2]), "r"((a)[3]),                 \
          "r"(b0), "r"(b1))

// ---------------------------------------------------------------------------
// Prologue kernels
// ---------------------------------------------------------------------------
__global__ void k_style(const float* __restrict__ latent,
                        const float* __restrict__ dense_w,
                        const float* __restrict__ dense_b) {
    const int n = blockIdx.x;
    const int c = threadIdx.x;
    const float* lp = latent + n * ZDIM;
    float a0 = 0.f, a1 = 0.f, a2 = 0.f, a3 = 0.f;
#pragma unroll 4
    for (int z = 0; z < ZDIM; z += 4) {
        a0 = fmaf(lp[z + 0], dense_w[(z + 0) * CINCH + c], a0);
        a1 = fmaf(lp[z + 1], dense_w[(z + 1) * CINCH + c], a1);
        a2 = fmaf(lp[z + 2], dense_w[(z + 2) * CINCH + c], a2);
        a3 = fmaf(lp[z + 3], dense_w[(z + 3) * CINCH + c], a3);
    }
    g_s[n * CINCH + c] = (a0 + a1 + a2 + a3) * DENSE_COEF + dense_b[c];
}

__global__ void k_w2(const float* __restrict__ conv_w) {
    const int i = blockIdx.x * 256 + threadIdx.x;
    float acc = 0.0f;
#pragma unroll
    for (int t = 0; t < 9; ++t) {
        float v = conv_w[t * (CINCH * COUTC) + i];
        acc = fmaf(v, v, acc);
    }
    g_w2[i] = acc * CONV_COEF2;
}

__global__ void k_demod() {
    __shared__ float s2[CINCH];
    const int n = blockIdx.x;
    const int c = threadIdx.x;
    float sv = g_s[n * CINCH + c];
    s2[c] = sv * sv;
    __syncthreads();
    float acc = 0.0f;
#pragma unroll 8
    for (int ci = 0; ci < CINCH; ++ci)
        acc = fmaf(s2[ci], g_w2[ci * COUTC + c], acc);
    g_d[n * COUTC + c] = rsqrtf(acc + 1e-8f);
}

// X = fp16(data * s)
__global__ void k_mod(const float* __restrict__ data) {
    const int e4 = blockIdx.x * 256 + threadIdx.x;      // float4 index
    const float4 v = ((const float4*)data)[e4];
    const int m = e4 >> 7;
    const int n = m >> 12;
    const int c = (e4 & 127) << 2;
    const float4 sv = *(const float4*)(g_s + n * CINCH + c);
    __half2 h0 = __floats2half2_rn(v.x * sv.x, v.y * sv.y);
    __half2 h1 = __floats2half2_rn(v.z * sv.z, v.w * sv.w);
    uint2 o;
    o.x = *(uint32_t*)&h0;
    o.y = *(uint32_t*)&h1;
    ((uint2*)g_X)[e4] = o;
}

// Bt[cout][tap*512+cin] = fp16(conv_w[tap][cin][cout] * CONV_COEF)
__global__ void k_transb(const float* __restrict__ conv_w) {
    __shared__ float t[32][33];
    const int cout0 = blockIdx.x * 32;
    const int cin0  = blockIdx.y * 32;
    const int tap   = blockIdx.z;
    const int tx = threadIdx.x;   // 0..31
    const int ty = threadIdx.y;   // 0..7
#pragma unroll
    for (int i = 0; i < 4; ++i) {
        int ci = ty + i * 8;
        t[ci][tx] = conv_w[((size_t)tap * CINCH + cin0 + ci) * COUTC + cout0 + tx];
    }
    __syncthreads();
#pragma unroll
    for (int i = 0; i < 4; ++i) {
        int co = ty + i * 8;
        g_Bt[(size_t)(cout0 + co) * KTOT + tap * CINCH + cin0 + tx] =
            __float2half_rn(t[tx][co] * CONV_COEF);
    }
}

// ---------------------------------------------------------------------------
// Staging: load k-stage s (tap, cin-chunk) into smem via cp.async
// ---------------------------------------------------------------------------
__device__ __forceinline__ void stage_load(uint32_t sA, uint32_t sB, int s,
                                           int tid, int n_img, int h0, int bn) {
    const int tap  = s >> 4;
    const int cin0 = (s & 15) * BK;
    const int dy = tap / 3 - 1;
    const int dx = tap % 3 - 1;

    // A: 128 rows x 4 chunks of 16B (8 halves each); 512 chunks / 256 thr = 2
#pragma unroll
    for (int i = 0; i < 2; ++i) {
        const int c  = tid + 256 * i;
        const int m  = c >> 2;
        const int ch = c & 3;
        const int h = h0 + (m >> 6) + dy;
        const int w = (m & 63) + dx;
        const bool v = ((unsigned)h < 64u) && ((unsigned)w < 64u);
        const int hc = v ? h : 0;
        const int wc = v ? w : 0;
        const __half* src = g_X + ((size_t)((n_img * 64 + hc) * 64 + wc)) * CINCH
                                + cin0 + ch * 8;
        cpa16(sA + m * ROWB + ch * 16, src, v ? 16u : 0u);
    }
    // B: 256 rows x 4 chunks of 16B; 1024 chunks / 256 thr = 4
#pragma unroll
    for (int i = 0; i < 4; ++i) {
        const int c  = tid + 256 * i;
        const int n  = c >> 2;
        const int ch = c & 3;
        const __half* src = g_Bt + (size_t)(bn + n) * KTOT + tap * CINCH + cin0 + ch * 8;
        cpa16(sB + n * ROWB + ch * 16, src, 16u);
    }
}

// ---------------------------------------------------------------------------
// Main kernel: fp16 mma.sync implicit GEMM + fused epilogue
// grid = (M_TOT/BM = 256, COUT/BN = 2), block = 256 (8 warps, 2x4)
// ---------------------------------------------------------------------------
__global__ void __launch_bounds__(256, 1)
k_conv_mma(const float* __restrict__ bias,
           const float* __restrict__ ncoef,
           const float* __restrict__ noise,
           float* __restrict__ out) {
    extern __shared__ char sm[];
    const uint32_t sbase = smem_u32(sm);

    const int tid  = threadIdx.x;
    const int wid  = tid >> 5;
    const int lane = tid & 31;
    const int gid  = lane >> 2;    // 0..7
    const int tid4 = lane & 3;     // 0..3
    const int l15  = lane & 15;
    const int lhi  = (lane >> 4) & 1;      // 0/1 -> +16B (k+8)
    const int wm = (wid >> 2) * 64;        // warp m-offset (0 or 64)
    const int wn = (wid & 3) * 64;         // warp n-offset (0,64,128,192)

    const int bm    = blockIdx.x * BM;
    const int bn    = blockIdx.y * BN;
    const int n_img = bm >> 12;
    const int h0    = (bm >> 6) & 63;

    float acc[4][8][4];
#pragma unroll
    for (int i = 0; i < 4; ++i)
#pragma unroll
        for (int j = 0; j < 8; ++j)
#pragma unroll
            for (int r = 0; r < 4; ++r) acc[i][j][r] = 0.0f;

    uint32_t sA[STAGES], sB[STAGES];
#pragma unroll
    for (int st = 0; st < STAGES; ++st) {
        sA[st] = sbase + st * STAGE_BYTES;
        sB[st] = sA[st] + A_ST_BYTES;
    }

    // prologue: fill stages 0,1,2
    stage_load(sA[0], sB[0], 0, tid, n_img, h0, bn);
    CP_COMMIT();
    stage_load(sA[1], sB[1], 1, tid, n_img, h0, bn);
    CP_COMMIT();
    stage_load(sA[2], sB[2], 2, tid, n_img, h0, bn);
    CP_COMMIT();

    // per-warp ldmatrix base offsets (row = l15, +16B when lane>=16)
    const uint32_t a_off = (uint32_t)(wm + l15) * ROWB + lhi * 16;
    const uint32_t b_off = (uint32_t)(wn + l15) * ROWB + lhi * 16;

    int buf = 0, nbuf = 3;
    for (int s = 0; s < NSTG_TOT; ++s) {
        CP_WAIT2();
        __syncthreads();

        if (s + 3 < NSTG_TOT)
            stage_load(sA[nbuf], sB[nbuf], s + 3, tid, n_img, h0, bn);
        CP_COMMIT();

        const uint32_t Ab = sA[buf] + a_off;
        const uint32_t Bb = sB[buf] + b_off;

#pragma unroll
        for (int kk = 0; kk < 2; ++kk) {
            uint32_t a[4][4];
#pragma unroll
            for (int i = 0; i < 4; ++i)
                LDMX4(a[i], Ab + i * (16 * ROWB) + kk * 32);
            uint32_t b[4][4];   // per j2: {b0_even, b0_odd, b1_even, b1_odd}
#pragma unroll
            for (int j2 = 0; j2 < 4; ++j2)
                LDMX4(b[j2], Bb + j2 * (16 * ROWB) + kk * 32);

#pragma unroll
            for (int i = 0; i < 4; ++i)
#pragma unroll
                for (int j = 0; j < 8; ++j) {
                    const int j2 = j >> 1, od = j & 1;
                    MMA_F16(acc[i][j], a[i], b[j2][od], b[j2][2 + od]);
                }
        }

        buf  = (buf == STAGES - 1) ? 0 : buf + 1;
        nbuf = (nbuf == STAGES - 1) ? 0 : nbuf + 1;
    }

    // ---------------- fused epilogue ----------------
    const float* d_row = g_d + n_img * COUTC;
#pragma unroll
    for (int j = 0; j < 8; ++j) {
        const int col = bn + wn + j * 8 + 2 * tid4;
        const float2 dv = *(const float2*)(d_row + col);
        const float2 bv = *(const float2*)(bias + col);
        const float2 cv = *(const float2*)(ncoef + col);
#pragma unroll
        for (int i = 0; i < 4; ++i) {
            const int r0 = bm + wm + i * 16 + gid;
#pragma unroll
            for (int half = 0; half < 2; ++half) {
                const int rr = r0 + half * 8;
                const float2 nz = *(const float2*)(noise + (size_t)rr * COUTC + col);
                float2 o;
                o.x = fmaf(acc[i][j][half * 2 + 0], dv.x, fmaf(nz.x, cv.x, bv.x));
                o.y = fmaf(acc[i][j][half * 2 + 1], dv.y, fmaf(nz.y, cv.y, bv.y));
                o.x = (o.x >= 0.f) ? o.x : 0.2f * o.x;
                o.y = (o.y >= 0.f) ? o.y : 0.2f * o.y;
                *(float2*)(out + (size_t)rr * COUTC + col) = o;
            }
        }
    }
}

// ---------------------------------------------------------------------------
// Launch
// ---------------------------------------------------------------------------
extern "C" void kernel_launch(void* const* d_in, const int* in_sizes, int n_in,
                              void* d_out, int out_size) {
    const float* data    = (const float*)d_in[0];
    const float* latent  = (const float*)d_in[1];
    const float* dense_w = (const float*)d_in[2];
    const float* dense_b = (const float*)d_in[3];
    const float* conv_w  = (const float*)d_in[4];
    const float* bias    = (const float*)d_in[5];
    const float* ncoef   = (const float*)d_in[6];
    const float* noise   = (const float*)d_in[7];
    float* out = (float*)d_out;

    static bool attr_set = false;
    if (!attr_set) {
        cudaFuncSetAttribute(k_conv_mma, cudaFuncAttributeMaxDynamicSharedMemorySize,
                             SMEM_TOTAL);
        attr_set = true;
    }

    k_style<<<NB, CINCH>>>(latent, dense_w, dense_b);
    k_w2<<<(CINCH * COUTC) / 256, 256>>>(conv_w);
    k_demod<<<NB, COUTC>>>();
    k_mod<<<(M_TOT * CINCH / 4) / 256, 256>>>(data);
    k_transb<<<dim3(COUTC / 32, CINCH / 32, 9), dim3(32, 8)>>>(conv_w);

    dim3 grid(M_TOT / BM, COUTC / BN);
    k_conv_mma<<<grid, 256, SMEM_TOTAL>>>(bias, ncoef, noise, out);
}

// round 5
// speedup vs baseline: 5.9279x; 1.1896x over previous
#include <cuda_runtime.h>
#include <cuda_fp16.h>
#include <cstdint>

// ---------------------------------------------------------------------------
// Problem constants
// ---------------------------------------------------------------------------
#define NB    8
#define CINCH 512
#define COUTC 512
#define ZDIM  512
#define M_TOT (NB * 64 * 64)        // 32768 pixels
#define KTOT  (9 * CINCH)           // 4608

#define DENSE_COEF (0.0625f)        // sqrt(2/512)
#define CONV_COEF  (1.0f / 48.0f)   // sqrt(2/4608)
#define CONV_COEF2 (1.0f / 2304.0f)

// GEMM tiling
#define BM 128
#define BN 128
#define BK 32
#define NSTG_TOT (KTOT / BK)        // 144 k-stages
#define STAGES 4
#define NTILES ((M_TOT / BM) * (COUTC / BN))   // 1024
#define GRID_P 304                  // persistent CTAs (2 per SM)

// smem rows: 32 halves (64B data) padded to 80B -> conflict-free ldmatrix
#define ROWB 80
#define A_ST_BYTES (BM * ROWB)      // 10240
#define B_ST_BYTES (BN * ROWB)      // 10240
#define STAGE_BYTES (A_ST_BYTES + B_ST_BYTES)   // 20480
#define SMEM_TOTAL (STAGES * STAGE_BYTES)       // 81920

// ---------------------------------------------------------------------------
// Scratch (device globals; no runtime allocation allowed)
// ---------------------------------------------------------------------------
__device__ float  g_s[NB * CINCH];
__device__ float  g_d[NB * COUTC];
__device__ float  g_w2[CINCH * COUTC];
__device__ __half g_X[M_TOT * CINCH];     // modulated input fp16, [m][cin]
__device__ __half g_Bt[COUTC * KTOT];     // weights fp16 K-major, [cout][tap*512+cin]
__device__ int    g_ctr;                  // persistent tile queue

// ---------------------------------------------------------------------------
// Helpers
// ---------------------------------------------------------------------------
__device__ __forceinline__ uint32_t smem_u32(const void* p) {
    uint32_t a;
    asm("{ .reg .u64 t; cvta.to.shared.u64 t, %1; cvt.u32.u64 %0, t; }" : "=r"(a) : "l"(p));
    return a;
}

__device__ __forceinline__ void cpa16(uint32_t dst, const void* src, uint32_t sz) {
    asm volatile("cp.async.cg.shared.global.L2::128B [%0], [%1], 16, %2;"
                 :: "r"(dst), "l"(src), "r"(sz) : "memory");
}

#define CP_COMMIT() asm volatile("cp.async.commit_group;" ::: "memory")
#define CP_WAIT2()  asm volatile("cp.async.wait_group 2;" ::: "memory")
#define CP_WAIT0()  asm volatile("cp.async.wait_group 0;" ::: "memory")

#define LDMX4(r, addr)                                                        \
    asm volatile("ldmatrix.sync.aligned.m8n8.x4.shared.b16 {%0,%1,%2,%3}, [%4];" \
                 : "=r"((r)[0]), "=r"((r)[1]), "=r"((r)[2]), "=r"((r)[3])     \
                 : "r"(addr))

#define MMA_F16(d, a, b0, b1)                                                 \
    asm volatile(                                                             \
        "mma.sync.aligned.m16n8k16.row.col.f32.f16.f16.f32 "                  \
        "{%0,%1,%2,%3}, {%4,%5,%6,%7}, {%8,%9}, {%0,%1,%2,%3};"               \
        : "+f"((d)[0]), "+f"((d)[1]), "+f"((d)[2]), "+f"((d)[3])              \
        : "r"((a)[0]), "r"((a)[1]), "r"((a)[2]), "r"((a)[3]),                 \
          "r"(b0), "r"(b1))

// ---------------------------------------------------------------------------
// Prologue kernels
// ---------------------------------------------------------------------------
__global__ void k_style(const float* __restrict__ latent,
                        const float* __restrict__ dense_w,
                        const float* __restrict__ dense_b) {
    if (blockIdx.x == 0 && threadIdx.x == 0) g_ctr = 0;   // reset tile queue
    const int n = blockIdx.x;
    const int c = threadIdx.x;
    const float* lp = latent + n * ZDIM;
    float a0 = 0.f, a1 = 0.f, a2 = 0.f, a3 = 0.f;
#pragma unroll 4
    for (int z = 0; z < ZDIM; z += 4) {
        a0 = fmaf(lp[z + 0], dense_w[(z + 0) * CINCH + c], a0);
        a1 = fmaf(lp[z + 1], dense_w[(z + 1) * CINCH + c], a1);
        a2 = fmaf(lp[z + 2], dense_w[(z + 2) * CINCH + c], a2);
        a3 = fmaf(lp[z + 3], dense_w[(z + 3) * CINCH + c], a3);
    }
    g_s[n * CINCH + c] = (a0 + a1 + a2 + a3) * DENSE_COEF + dense_b[c];
}

__global__ void k_w2(const float* __restrict__ conv_w) {
    const int i = blockIdx.x * 256 + threadIdx.x;
    float acc = 0.0f;
#pragma unroll
    for (int t = 0; t < 9; ++t) {
        float v = conv_w[t * (CINCH * COUTC) + i];
        acc = fmaf(v, v, acc);
    }
    g_w2[i] = acc * CONV_COEF2;
}

__global__ void k_demod() {
    __shared__ float s2[CINCH];
    const int n = blockIdx.x;
    const int c = threadIdx.x;
    float sv = g_s[n * CINCH + c];
    s2[c] = sv * sv;
    __syncthreads();
    float acc = 0.0f;
#pragma unroll 8
    for (int ci = 0; ci < CINCH; ++ci)
        acc = fmaf(s2[ci], g_w2[ci * COUTC + c], acc);
    g_d[n * COUTC + c] = rsqrtf(acc + 1e-8f);
}

// X = fp16(data * s)
__global__ void k_mod(const float* __restrict__ data) {
    const int e4 = blockIdx.x * 256 + threadIdx.x;
    const float4 v = ((const float4*)data)[e4];
    const int m = e4 >> 7;
    const int n = m >> 12;
    const int c = (e4 & 127) << 2;
    const float4 sv = *(const float4*)(g_s + n * CINCH + c);
    __half2 h0 = __floats2half2_rn(v.x * sv.x, v.y * sv.y);
    __half2 h1 = __floats2half2_rn(v.z * sv.z, v.w * sv.w);
    uint2 o;
    o.x = *(uint32_t*)&h0;
    o.y = *(uint32_t*)&h1;
    ((uint2*)g_X)[e4] = o;
}

// Bt[cout][tap*512+cin] = fp16(conv_w[tap][cin][cout] * CONV_COEF)
__global__ void k_transb(const float* __restrict__ conv_w) {
    __shared__ float t[32][33];
    const int cout0 = blockIdx.x * 32;
    const int cin0  = blockIdx.y * 32;
    const int tap   = blockIdx.z;
    const int tx = threadIdx.x;
    const int ty = threadIdx.y;
#pragma unroll
    for (int i = 0; i < 4; ++i) {
        int ci = ty + i * 8;
        t[ci][tx] = conv_w[((size_t)tap * CINCH + cin0 + ci) * COUTC + cout0 + tx];
    }
    __syncthreads();
#pragma unroll
    for (int i = 0; i < 4; ++i) {
        int co = ty + i * 8;
        g_Bt[(size_t)(cout0 + co) * KTOT + tap * CINCH + cin0 + tx] =
            __float2half_rn(t[tx][co] * CONV_COEF);
    }
}

// ---------------------------------------------------------------------------
// Staging: load k-stage s (tap, cin-chunk) into smem via cp.async
// ---------------------------------------------------------------------------
__device__ __forceinline__ void stage_load(uint32_t sA, uint32_t sB, int s,
                                           int tid, int n_img, int h0, int bn) {
    const int tap  = s >> 4;
    const int cin0 = (s & 15) * BK;
    const int dy = tap / 3 - 1;
    const int dx = tap % 3 - 1;

    // A: 128 rows x 4 chunks of 16B; 512 chunks / 256 thr = 2
#pragma unroll
    for (int i = 0; i < 2; ++i) {
        const int c  = tid + 256 * i;
        const int m  = c >> 2;
        const int ch = c & 3;
        const int h = h0 + (m >> 6) + dy;
        const int w = (m & 63) + dx;
        const bool v = ((unsigned)h < 64u) && ((unsigned)w < 64u);
        const int hc = v ? h : 0;
        const int wc = v ? w : 0;
        const __half* src = g_X + ((size_t)((n_img * 64 + hc) * 64 + wc)) * CINCH
                                + cin0 + ch * 8;
        cpa16(sA + m * ROWB + ch * 16, src, v ? 16u : 0u);
    }
    // B: 128 rows x 4 chunks of 16B; 512 chunks / 256 thr = 2
#pragma unroll
    for (int i = 0; i < 2; ++i) {
        const int c  = tid + 256 * i;
        const int n  = c >> 2;
        const int ch = c & 3;
        const __half* src = g_Bt + (size_t)(bn + n) * KTOT + tap * CINCH + cin0 + ch * 8;
        cpa16(sB + n * ROWB + ch * 16, src, 16u);
    }
}

// ---------------------------------------------------------------------------
// Main kernel: persistent fp16 mma.sync implicit GEMM + fused epilogue
// grid = 304 (2 CTAs/SM), block = 256 (8 warps, 2x4), tile = 128x128
// ---------------------------------------------------------------------------
__global__ void __launch_bounds__(256, 2)
k_conv_mma(const float* __restrict__ bias,
           const float* __restrict__ ncoef,
           const float* __restrict__ noise,
           float* __restrict__ out) {
    extern __shared__ char sm[];
    __shared__ int s_tile;
    const uint32_t sbase = smem_u32(sm);

    const int tid  = threadIdx.x;
    const int wid  = tid >> 5;
    const int lane = tid & 31;
    const int gid  = lane >> 2;
    const int tid4 = lane & 3;
    const int l15  = lane & 15;
    const int lhi  = (lane >> 4) & 1;
    const int wm = (wid >> 2) * 64;        // warp m-offset (0 or 64)
    const int wn = (wid & 3) * 32;         // warp n-offset (0,32,64,96)

    uint32_t sA[STAGES], sB[STAGES];
#pragma unroll
    for (int st = 0; st < STAGES; ++st) {
        sA[st] = sbase + st * STAGE_BYTES;
        sB[st] = sA[st] + A_ST_BYTES;
    }
    const uint32_t a_off = (uint32_t)(wm + l15) * ROWB + lhi * 16;
    const uint32_t b_off = (uint32_t)(wn + l15) * ROWB + lhi * 16;

    for (;;) {
        // drain pending cp.async from previous tile, then fetch next tile id
        CP_WAIT0();
        __syncthreads();
        if (tid == 0) s_tile = atomicAdd(&g_ctr, 1);
        __syncthreads();
        const int t = s_tile;
        if (t >= NTILES) break;

        const int bm    = (t >> 2) * BM;   // consecutive tiles share the A m-tile
        const int bn    = (t & 3) * BN;
        const int n_img = bm >> 12;
        const int h0    = (bm >> 6) & 63;

        float acc[4][4][4];
#pragma unroll
        for (int i = 0; i < 4; ++i)
#pragma unroll
            for (int j = 0; j < 4; ++j)
#pragma unroll
                for (int r = 0; r < 4; ++r) acc[i][j][r] = 0.0f;

        stage_load(sA[0], sB[0], 0, tid, n_img, h0, bn);
        CP_COMMIT();
        stage_load(sA[1], sB[1], 1, tid, n_img, h0, bn);
        CP_COMMIT();
        stage_load(sA[2], sB[2], 2, tid, n_img, h0, bn);
        CP_COMMIT();

        int buf = 0, nbuf = 3;
        for (int s = 0; s < NSTG_TOT; ++s) {
            CP_WAIT2();
            __syncthreads();

            if (s + 3 < NSTG_TOT)
                stage_load(sA[nbuf], sB[nbuf], s + 3, tid, n_img, h0, bn);
            CP_COMMIT();

            const uint32_t Ab = sA[buf] + a_off;
            const uint32_t Bb = sB[buf] + b_off;

#pragma unroll
            for (int kk = 0; kk < 2; ++kk) {
                uint32_t a[4][4];
#pragma unroll
                for (int i = 0; i < 4; ++i)
                    LDMX4(a[i], Ab + i * (16 * ROWB) + kk * 32);
                uint32_t b[2][4];
#pragma unroll
                for (int j2 = 0; j2 < 2; ++j2)
                    LDMX4(b[j2], Bb + j2 * (16 * ROWB) + kk * 32);

#pragma unroll
                for (int i = 0; i < 4; ++i)
#pragma unroll
                    for (int j = 0; j < 4; ++j) {
                        const int j2 = j >> 1, od = j & 1;
                        MMA_F16(acc[i][j], a[i], b[j2][od], b[j2][2 + od]);
                    }
            }

            buf  = (buf == STAGES - 1) ? 0 : buf + 1;
            nbuf = (nbuf == STAGES - 1) ? 0 : nbuf + 1;
        }

        // ---------------- fused epilogue ----------------
        const float* d_row = g_d + n_img * COUTC;
#pragma unroll
        for (int j = 0; j < 4; ++j) {
            const int col = bn + wn + j * 8 + 2 * tid4;
            const float2 dv = *(const float2*)(d_row + col);
            const float2 bv = *(const float2*)(bias + col);
            const float2 cv = *(const float2*)(ncoef + col);
#pragma unroll
            for (int i = 0; i < 4; ++i) {
                const int r0 = bm + wm + i * 16 + gid;
#pragma unroll
                for (int half = 0; half < 2; ++half) {
                    const int rr = r0 + half * 8;
                    const float2 nz = *(const float2*)(noise + (size_t)rr * COUTC + col);
                    float2 o;
                    o.x = fmaf(acc[i][j][half * 2 + 0], dv.x, fmaf(nz.x, cv.x, bv.x));
                    o.y = fmaf(acc[i][j][half * 2 + 1], dv.y, fmaf(nz.y, cv.y, bv.y));
                    o.x = (o.x >= 0.f) ? o.x : 0.2f * o.x;
                    o.y = (o.y >= 0.f) ? o.y : 0.2f * o.y;
                    *(float2*)(out + (size_t)rr * COUTC + col) = o;
                }
            }
        }
    }
}

// ---------------------------------------------------------------------------
// Launch
// ---------------------------------------------------------------------------
extern "C" void kernel_launch(void* const* d_in, const int* in_sizes, int n_in,
                              void* d_out, int out_size) {
    const float* data    = (const float*)d_in[0];
    const float* latent  = (const float*)d_in[1];
    const float* dense_w = (const float*)d_in[2];
    const float* dense_b = (const float*)d_in[3];
    const float* conv_w  = (const float*)d_in[4];
    const float* bias    = (const float*)d_in[5];
    const float* ncoef   = (const float*)d_in[6];
    const float* noise   = (const float*)d_in[7];
    float* out = (float*)d_out;

    static bool attr_set = false;
    if (!attr_set) {
        cudaFuncSetAttribute(k_conv_mma, cudaFuncAttributeMaxDynamicSharedMemorySize,
                             SMEM_TOTAL);
        attr_set = true;
    }

    k_style<<<NB, CINCH>>>(latent, dense_w, dense_b);
    k_w2<<<(CINCH * COUTC) / 256, 256>>>(conv_w);
    k_demod<<<NB, COUTC>>>();
    k_mod<<<(M_TOT * CINCH / 4) / 256, 256>>>(data);
    k_transb<<<dim3(COUTC / 32, CINCH / 32, 9), dim3(32, 8)>>>(conv_w);

    k_conv_mma<<<GRID_P, 256, SMEM_TOTAL>>>(bias, ncoef, noise, out);
}

// round 6
// speedup vs baseline: 8.9721x; 1.5135x over previous
#include <cuda_runtime.h>
#include <cuda_fp16.h>
#include <cstdint>

// ---------------------------------------------------------------------------
// Problem constants
// ---------------------------------------------------------------------------
#define NB    8
#define CINCH 512
#define COUTC 512
#define ZDIM  512
#define M_TOT (NB * 64 * 64)        // 32768 pixels
#define P_TILES 8192                // 8 images * 32*32 Winograd tiles (2x2 out)

#define DENSE_COEF (0.0625f)        // sqrt(2/512)
#define CONV_COEF  (1.0f / 48.0f)   // sqrt(2/4608)
#define CONV_COEF2 (1.0f / 2304.0f)

// Winograd-domain GEMM tiling: per pos, [8192 x 512] * [512 x 512]
#define BM 128
#define BN 128
#define BK 32
#define NSTG 16                     // 512 / 32 k-stages per tile
#define STAGES 4
#define NTILES_G (16 * (P_TILES / BM) * (COUTC / BN))   // 16*64*4 = 4096
#define GRID_P 304                  // persistent CTAs (2 per SM)

// smem rows: 32 halves (64B data) padded to 80B -> conflict-free ldmatrix
#define ROWB 80
#define A_ST_BYTES (BM * ROWB)      // 10240
#define B_ST_BYTES (BN * ROWB)      // 10240
#define STAGE_BYTES (A_ST_BYTES + B_ST_BYTES)   // 20480
#define SMEM_TOTAL (STAGES * STAGE_BYTES)       // 81920

// ---------------------------------------------------------------------------
// Scratch (device globals; no runtime allocation allowed)
// ---------------------------------------------------------------------------
__device__ float  g_s[NB * CINCH];
__device__ float  g_d[NB * COUTC];
__device__ float  g_w2[CINCH * COUTC];
__device__ __half g_V[16 * P_TILES * CINCH];    // input transform  [pos][p][cin]
__device__ __half g_U[16 * CINCH * COUTC];      // weight transform [pos][cout][cin]
__device__ float  g_M[16 * P_TILES * COUTC];    // GEMM out         [pos][p][cout]
__device__ int    g_ctr;                        // persistent tile queue

// ---------------------------------------------------------------------------
// Helpers
// ---------------------------------------------------------------------------
__device__ __forceinline__ uint32_t smem_u32(const void* p) {
    uint32_t a;
    asm("{ .reg .u64 t; cvta.to.shared.u64 t, %1; cvt.u32.u64 %0, t; }" : "=r"(a) : "l"(p));
    return a;
}

__device__ __forceinline__ void cpa16(uint32_t dst, const void* src) {
    asm volatile("cp.async.cg.shared.global.L2::128B [%0], [%1], 16;"
                 :: "r"(dst), "l"(src) : "memory");
}

#define CP_COMMIT() asm volatile("cp.async.commit_group;" ::: "memory")
#define CP_WAIT2()  asm volatile("cp.async.wait_group 2;" ::: "memory")
#define CP_WAIT0()  asm volatile("cp.async.wait_group 0;" ::: "memory")

#define LDMX4(r, addr)                                                        \
    asm volatile("ldmatrix.sync.aligned.m8n8.x4.shared.b16 {%0,%1,%2,%3}, [%4];" \
                 : "=r"((r)[0]), "=r"((r)[1]), "=r"((r)[2]), "=r"((r)[3])     \
                 : "r"(addr))

#define MMA_F16(d, a, b0, b1)                                                 \
    asm volatile(                                                             \
        "mma.sync.aligned.m16n8k16.row.col.f32.f16.f16.f32 "                  \
        "{%0,%1,%2,%3}, {%4,%5,%6,%7}, {%8,%9}, {%0,%1,%2,%3};"               \
        : "+f"((d)[0]), "+f"((d)[1]), "+f"((d)[2]), "+f"((d)[3])              \
        : "r"((a)[0]), "r"((a)[1]), "r"((a)[2]), "r"((a)[3]),                 \
          "r"(b0), "r"(b1))

// ---------------------------------------------------------------------------
// Prologue: style vector, w^2 reduction, demod
// ---------------------------------------------------------------------------
__global__ void k_style(const float* __restrict__ latent,
                        const float* __restrict__ dense_w,
                        const float* __restrict__ dense_b) {
    if (blockIdx.x == 0 && threadIdx.x == 0) g_ctr = 0;   // reset tile queue
    const int n = blockIdx.x;
    const int c = threadIdx.x;
    const float* lp = latent + n * ZDIM;
    float a0 = 0.f, a1 = 0.f, a2 = 0.f, a3 = 0.f;
#pragma unroll 4
    for (int z = 0; z < ZDIM; z += 4) {
        a0 = fmaf(lp[z + 0], dense_w[(z + 0) * CINCH + c], a0);
        a1 = fmaf(lp[z + 1], dense_w[(z + 1) * CINCH + c], a1);
        a2 = fmaf(lp[z + 2], dense_w[(z + 2) * CINCH + c], a2);
        a3 = fmaf(lp[z + 3], dense_w[(z + 3) * CINCH + c], a3);
    }
    g_s[n * CINCH + c] = (a0 + a1 + a2 + a3) * DENSE_COEF + dense_b[c];
}

__global__ void k_w2(const float* __restrict__ conv_w) {
    const int i = blockIdx.x * 256 + threadIdx.x;
    float acc = 0.0f;
#pragma unroll
    for (int t = 0; t < 9; ++t) {
        float v = conv_w[t * (CINCH * COUTC) + i];
        acc = fmaf(v, v, acc);
    }
    g_w2[i] = acc * CONV_COEF2;
}

__global__ void k_demod() {
    __shared__ float s2[CINCH];
    const int n = blockIdx.x;
    const int c = threadIdx.x;
    float sv = g_s[n * CINCH + c];
    s2[c] = sv * sv;
    __syncthreads();
    float acc = 0.0f;
#pragma unroll 8
    for (int ci = 0; ci < CINCH; ++ci)
        acc = fmaf(s2[ci], g_w2[ci * COUTC + c], acc);
    g_d[n * COUTC + c] = rsqrtf(acc + 1e-8f);
}

// ---------------------------------------------------------------------------
// Weight transform: U[pos][cout][cin] = (G (w*coef) G^T)[pos], fp16
// grid (16,16), block (32,8): 32x32 (cin,cout) tile, smem transpose
// ---------------------------------------------------------------------------
__global__ void k_wino_u(const float* __restrict__ conv_w) {
    __shared__ float tw[9][32][33];
    const int ci0 = blockIdx.x * 32;
    const int co0 = blockIdx.y * 32;
    const int tx = threadIdx.x;   // 0..31
    const int ty = threadIdx.y;   // 0..7
#pragma unroll
    for (int t = 0; t < 9; ++t)
#pragma unroll
        for (int i = 0; i < 4; ++i) {
            const int ci = ty + i * 8;
            tw[t][ci][tx] = conv_w[((size_t)t * CINCH + ci0 + ci) * COUTC + co0 + tx];
        }
    __syncthreads();
#pragma unroll
    for (int i = 0; i < 4; ++i) {
        const int co_l = ty + i * 8;
        float g[3][3];
#pragma unroll
        for (int k = 0; k < 9; ++k)
            g[k / 3][k % 3] = tw[k][tx][co_l] * CONV_COEF;
        float tg[4][3];
#pragma unroll
        for (int c = 0; c < 3; ++c) {
            tg[0][c] = g[0][c];
            tg[1][c] = 0.5f * (g[0][c] + g[1][c] + g[2][c]);
            tg[2][c] = 0.5f * (g[0][c] - g[1][c] + g[2][c]);
            tg[3][c] = g[2][c];
        }
        const size_t b = (size_t)(co0 + co_l) * CINCH + ci0 + tx;
#pragma unroll
        for (int r = 0; r < 4; ++r) {
            const float u0 = tg[r][0];
            const float u1 = 0.5f * (tg[r][0] + tg[r][1] + tg[r][2]);
            const float u2 = 0.5f * (tg[r][0] - tg[r][1] + tg[r][2]);
            const float u3 = tg[r][2];
            g_U[(size_t)(r * 4 + 0) * (CINCH * COUTC) + b] = __float2half_rn(u0);
            g_U[(size_t)(r * 4 + 1) * (CINCH * COUTC) + b] = __float2half_rn(u1);
            g_U[(size_t)(r * 4 + 2) * (CINCH * COUTC) + b] = __float2half_rn(u2);
            g_U[(size_t)(r * 4 + 3) * (CINCH * COUTC) + b] = __float2half_rn(u3);
        }
    }
}

// ---------------------------------------------------------------------------
// Input transform fused with modulation: V[pos][p][cin] = B^T (x*s) B, fp16
// grid = 8192 (one Winograd tile per block), block = 512 (one cin per thread)
// ---------------------------------------------------------------------------
__global__ void k_wino_v(const float* __restrict__ data) {
    const int p  = blockIdx.x;
    const int ci = threadIdx.x;
    const int n  = p >> 10;
    const int ty = (p >> 5) & 31;
    const int tx = p & 31;
    const int y0 = 2 * ty - 1;
    const int x0 = 2 * tx - 1;
    const float sv = g_s[n * CINCH + ci];

    float d[4][4];
#pragma unroll
    for (int r = 0; r < 4; ++r) {
        const int h = y0 + r;
        const bool hv = (unsigned)h < 64u;
#pragma unroll
        for (int c = 0; c < 4; ++c) {
            const int w = x0 + c;
            float v = 0.f;
            if (hv && (unsigned)w < 64u)
                v = data[((size_t)((n * 64 + h) * 64 + w)) * CINCH + ci] * sv;
            d[r][c] = v;
        }
    }
    // t = B^T d   (rows)
    float t[4][4];
#pragma unroll
    for (int c = 0; c < 4; ++c) {
        t[0][c] = d[0][c] - d[2][c];
        t[1][c] = d[1][c] + d[2][c];
        t[2][c] = d[2][c] - d[1][c];
        t[3][c] = d[1][c] - d[3][c];
    }
    // v = t B   (cols), write per pos
    const size_t pb = (size_t)p * CINCH + ci;
#pragma unroll
    for (int r = 0; r < 4; ++r) {
        const float v0 = t[r][0] - t[r][2];
        const float v1 = t[r][1] + t[r][2];
        const float v2 = t[r][2] - t[r][1];
        const float v3 = t[r][1] - t[r][3];
        const size_t ps = (size_t)P_TILES * CINCH;
        g_V[(size_t)(r * 4 + 0) * ps + pb] = __float2half_rn(v0);
        g_V[(size_t)(r * 4 + 1) * ps + pb] = __float2half_rn(v1);
        g_V[(size_t)(r * 4 + 2) * ps + pb] = __float2half_rn(v2);
        g_V[(size_t)(r * 4 + 3) * ps + pb] = __float2half_rn(v3);
    }
}

// ---------------------------------------------------------------------------
// Staging for the Winograd-domain GEMM
// ---------------------------------------------------------------------------
__device__ __forceinline__ void stage_load(uint32_t sA, uint32_t sB, int s,
                                           int tid, int pos, int bm, int bn) {
    const int ci0 = s * BK;
    const __half* va = g_V + (size_t)pos * (P_TILES * CINCH);
    const __half* ub = g_U + (size_t)pos * (CINCH * COUTC);
    // A: 128 rows x 4 chunks of 16B; 512 chunks / 256 thr = 2
#pragma unroll
    for (int i = 0; i < 2; ++i) {
        const int c  = tid + 256 * i;
        const int m  = c >> 2;
        const int ch = c & 3;
        cpa16(sA + m * ROWB + ch * 16,
              va + (size_t)(bm + m) * CINCH + ci0 + ch * 8);
    }
    // B: 128 rows x 4 chunks of 16B
#pragma unroll
    for (int i = 0; i < 2; ++i) {
        const int c  = tid + 256 * i;
        const int nn = c >> 2;
        const int ch = c & 3;
        cpa16(sB + nn * ROWB + ch * 16,
              ub + (size_t)(bn + nn) * CINCH + ci0 + ch * 8);
    }
}

// ---------------------------------------------------------------------------
// Winograd-domain GEMM: 16 x [8192 x 512 x 512], persistent fp16 mma.sync
// grid = 304, block = 256 (8 warps, 2x4), tile 128x128, M fp32 out
// ---------------------------------------------------------------------------
__global__ void __launch_bounds__(256, 2)
k_wino_gemm() {
    extern __shared__ char sm[];
    __shared__ int s_tile;
    const uint32_t sbase = smem_u32(sm);

    const int tid  = threadIdx.x;
    const int wid  = tid >> 5;
    const int lane = tid & 31;
    const int gid  = lane >> 2;
    const int tid4 = lane & 3;
    const int l15  = lane & 15;
    const int lhi  = (lane >> 4) & 1;
    const int wm = (wid >> 2) * 64;
    const int wn = (wid & 3) * 32;

    uint32_t sA[STAGES], sB[STAGES];
#pragma unroll
    for (int st = 0; st < STAGES; ++st) {
        sA[st] = sbase + st * STAGE_BYTES;
        sB[st] = sA[st] + A_ST_BYTES;
    }
    const uint32_t a_off = (uint32_t)(wm + l15) * ROWB + lhi * 16;
    const uint32_t b_off = (uint32_t)(wn + l15) * ROWB + lhi * 16;

    for (;;) {
        CP_WAIT0();
        __syncthreads();
        if (tid == 0) s_tile = atomicAdd(&g_ctr, 1);
        __syncthreads();
        const int t = s_tile;
        if (t >= NTILES_G) break;

        const int bn  = (t & 3) * BN;
        const int bm  = ((t >> 2) & 63) * BM;
        const int pos = t >> 8;               // 256 consecutive tiles share pos

        float acc[4][4][4];
#pragma unroll
        for (int i = 0; i < 4; ++i)
#pragma unroll
            for (int j = 0; j < 4; ++j)
#pragma unroll
                for (int r = 0; r < 4; ++r) acc[i][j][r] = 0.0f;

        stage_load(sA[0], sB[0], 0, tid, pos, bm, bn);
        CP_COMMIT();
        stage_load(sA[1], sB[1], 1, tid, pos, bm, bn);
        CP_COMMIT();
        stage_load(sA[2], sB[2], 2, tid, pos, bm, bn);
        CP_COMMIT();

        int buf = 0, nbuf = 3;
        for (int s = 0; s < NSTG; ++s) {
            CP_WAIT2();
            __syncthreads();

            if (s + 3 < NSTG)
                stage_load(sA[nbuf], sB[nbuf], s + 3, tid, pos, bm, bn);
            CP_COMMIT();

            const uint32_t Ab = sA[buf] + a_off;
            const uint32_t Bb = sB[buf] + b_off;

#pragma unroll
            for (int kk = 0; kk < 2; ++kk) {
                uint32_t a[4][4];
#pragma unroll
                for (int i = 0; i < 4; ++i)
                    LDMX4(a[i], Ab + i * (16 * ROWB) + kk * 32);
                uint32_t b[2][4];
#pragma unroll
                for (int j2 = 0; j2 < 2; ++j2)
                    LDMX4(b[j2], Bb + j2 * (16 * ROWB) + kk * 32);

#pragma unroll
                for (int i = 0; i < 4; ++i)
#pragma unroll
                    for (int j = 0; j < 4; ++j) {
                        const int j2 = j >> 1, od = j & 1;
                        MMA_F16(acc[i][j], a[i], b[j2][od], b[j2][2 + od]);
                    }
            }

            buf  = (buf == STAGES - 1) ? 0 : buf + 1;
            nbuf = (nbuf == STAGES - 1) ? 0 : nbuf + 1;
        }

        // write M (fp32)
        float* mb = g_M + (size_t)pos * (P_TILES * COUTC);
#pragma unroll
        for (int j = 0; j < 4; ++j) {
            const int col = bn + wn + j * 8 + 2 * tid4;
#pragma unroll
            for (int i = 0; i < 4; ++i) {
                const int r0 = bm + wm + i * 16 + gid;
#pragma unroll
                for (int half = 0; half < 2; ++half) {
                    const int rr = r0 + half * 8;
                    float2 o;
                    o.x = acc[i][j][half * 2 + 0];
                    o.y = acc[i][j][half * 2 + 1];
                    *(float2*)(mb + (size_t)rr * COUTC + col) = o;
                }
            }
        }
    }
}

// ---------------------------------------------------------------------------
// Inverse transform + fused epilogue (demod, bias, noise, leaky)
// grid = 8192 (tile per block), block = 512 (cout per thread)
// ---------------------------------------------------------------------------
__global__ void k_wino_out(const float* __restrict__ bias,
                           const float* __restrict__ ncoef,
                           const float* __restrict__ noise,
                           float* __restrict__ out) {
    const int p  = blockIdx.x;
    const int co = threadIdx.x;
    const int n  = p >> 10;
    const int ty = (p >> 5) & 31;
    const int tx = p & 31;

    float m[4][4];
    const size_t pb = (size_t)p * COUTC + co;
#pragma unroll
    for (int pos = 0; pos < 16; ++pos)
        m[pos >> 2][pos & 3] = g_M[(size_t)pos * (P_TILES * COUTC) + pb];

    float t0[4], t1[4];
#pragma unroll
    for (int c = 0; c < 4; ++c) {
        t0[c] = m[0][c] + m[1][c] + m[2][c];
        t1[c] = m[1][c] - m[2][c] - m[3][c];
    }
    float y[2][2];
    y[0][0] = t0[0] + t0[1] + t0[2];
    y[0][1] = t0[1] - t0[2] - t0[3];
    y[1][0] = t1[0] + t1[1] + t1[2];
    y[1][1] = t1[1] - t1[2] - t1[3];

    const float dv = g_d[n * COUTC + co];
    const float bv = bias[co];
    const float cv = ncoef[co];
#pragma unroll
    for (int r = 0; r < 2; ++r)
#pragma unroll
        for (int c = 0; c < 2; ++c) {
            const int h = 2 * ty + r;
            const int w = 2 * tx + c;
            const size_t idx = ((size_t)((n * 64 + h) * 64 + w)) * COUTC + co;
            float o = fmaf(y[r][c], dv, fmaf(noise[idx], cv, bv));
            o = (o >= 0.f) ? o : 0.2f * o;
            out[idx] = o;
        }
}

// ---------------------------------------------------------------------------
// Launch
// ---------------------------------------------------------------------------
extern "C" void kernel_launch(void* const* d_in, const int* in_sizes, int n_in,
                              void* d_out, int out_size) {
    const float* data    = (const float*)d_in[0];
    const float* latent  = (const float*)d_in[1];
    const float* dense_w = (const float*)d_in[2];
    const float* dense_b = (const float*)d_in[3];
    const float* conv_w  = (const float*)d_in[4];
    const float* bias    = (const float*)d_in[5];
    const float* ncoef   = (const float*)d_in[6];
    const float* noise   = (const float*)d_in[7];
    float* out = (float*)d_out;

    static bool attr_set = false;
    if (!attr_set) {
        cudaFuncSetAttribute(k_wino_gemm, cudaFuncAttributeMaxDynamicSharedMemorySize,
                             SMEM_TOTAL);
        attr_set = true;
    }

    k_style<<<NB, CINCH>>>(latent, dense_w, dense_b);
    k_w2<<<(CINCH * COUTC) / 256, 256>>>(conv_w);
    k_demod<<<NB, COUTC>>>();
    k_wino_u<<<dim3(CINCH / 32, COUTC / 32), dim3(32, 8)>>>(conv_w);
    k_wino_v<<<P_TILES, CINCH>>>(data);
    k_wino_gemm<<<GRID_P, 256, SMEM_TOTAL>>>();
    k_wino_out<<<P_TILES, COUTC>>>(bias, ncoef, noise, out);
}

// round 7
// speedup vs baseline: 9.7286x; 1.0843x over previous
#include <cuda_runtime.h>
#include <cuda_fp16.h>
#include <cstdint>

// ---------------------------------------------------------------------------
// Problem constants
// ---------------------------------------------------------------------------
#define NB    8
#define CINCH 512
#define COUTC 512
#define ZDIM  512
#define M_TOT (NB * 64 * 64)        // 32768 pixels
#define P_TILES 8192                // 8 images * 32*32 Winograd tiles (2x2 out)

#define DENSE_COEF (0.0625f)        // sqrt(2/512)
#define CONV_COEF  (1.0f / 48.0f)   // sqrt(2/4608)
#define CONV_COEF2 (1.0f / 2304.0f)

// Winograd-domain GEMM tiling: per pos, [8192 x 512] * [512 x 512]
#define BM 128
#define BN 128
#define BK 32
#define NSTG 16                     // 512 / 32 k-stages per tile
#define STAGES 4
#define NTILES_G (16 * (P_TILES / BM) * (COUTC / BN))   // 4096
#define GRID_P 304                  // persistent CTAs (2 per SM)

// smem rows: 32 halves (64B data) padded to 80B -> conflict-free ldmatrix
#define ROWB 80
#define A_ST_BYTES (BM * ROWB)      // 10240
#define B_ST_BYTES (BN * ROWB)      // 10240
#define STAGE_BYTES (A_ST_BYTES + B_ST_BYTES)   // 20480
#define SMEM_TOTAL (STAGES * STAGE_BYTES)       // 81920

// ---------------------------------------------------------------------------
// Scratch (device globals; no runtime allocation allowed)
// ---------------------------------------------------------------------------
__device__ float  g_s[NB * CINCH];
__device__ float  g_d[NB * COUTC];
__device__ float  g_w2[CINCH * COUTC];
__device__ __half g_V[16 * P_TILES * CINCH];    // input transform  [pos][p][cin]
__device__ __half g_U[16 * CINCH * COUTC];      // weight transform [pos][cout][cin]
__device__ __half g_M[16 * P_TILES * COUTC];    // GEMM out fp16    [pos][p][cout]
__device__ int    g_ctr;                        // persistent tile queue

// ---------------------------------------------------------------------------
// Helpers
// ---------------------------------------------------------------------------
__device__ __forceinline__ uint32_t smem_u32(const void* p) {
    uint32_t a;
    asm("{ .reg .u64 t; cvta.to.shared.u64 t, %1; cvt.u32.u64 %0, t; }" : "=r"(a) : "l"(p));
    return a;
}

__device__ __forceinline__ void cpa16(uint32_t dst, const void* src) {
    asm volatile("cp.async.cg.shared.global.L2::128B [%0], [%1], 16;"
                 :: "r"(dst), "l"(src) : "memory");
}

#define CP_COMMIT() asm volatile("cp.async.commit_group;" ::: "memory")
#define CP_WAIT2()  asm volatile("cp.async.wait_group 2;" ::: "memory")
#define CP_WAIT0()  asm volatile("cp.async.wait_group 0;" ::: "memory")

#define LDMX4(r, addr)                                                        \
    asm volatile("ldmatrix.sync.aligned.m8n8.x4.shared.b16 {%0,%1,%2,%3}, [%4];" \
                 : "=r"((r)[0]), "=r"((r)[1]), "=r"((r)[2]), "=r"((r)[3])     \
                 : "r"(addr))

#define MMA_F16(d, a, b0, b1)                                                 \
    asm volatile(                                                             \
        "mma.sync.aligned.m16n8k16.row.col.f32.f16.f16.f32 "                  \
        "{%0,%1,%2,%3}, {%4,%5,%6,%7}, {%8,%9}, {%0,%1,%2,%3};"               \
        : "+f"((d)[0]), "+f"((d)[1]), "+f"((d)[2]), "+f"((d)[3])              \
        : "r"((a)[0]), "r"((a)[1]), "r"((a)[2]), "r"((a)[3]),                 \
          "r"(b0), "r"(b1))

// ---------------------------------------------------------------------------
// Prologue: style vector, w^2 reduction, demod
// ---------------------------------------------------------------------------
__global__ void k_style(const float* __restrict__ latent,
                        const float* __restrict__ dense_w,
                        const float* __restrict__ dense_b) {
    if (blockIdx.x == 0 && threadIdx.x == 0) g_ctr = 0;   // reset tile queue
    const int n = blockIdx.x;
    const int c = threadIdx.x;
    const float* lp = latent + n * ZDIM;
    float a0 = 0.f, a1 = 0.f, a2 = 0.f, a3 = 0.f;
#pragma unroll 4
    for (int z = 0; z < ZDIM; z += 4) {
        a0 = fmaf(lp[z + 0], dense_w[(z + 0) * CINCH + c], a0);
        a1 = fmaf(lp[z + 1], dense_w[(z + 1) * CINCH + c], a1);
        a2 = fmaf(lp[z + 2], dense_w[(z + 2) * CINCH + c], a2);
        a3 = fmaf(lp[z + 3], dense_w[(z + 3) * CINCH + c], a3);
    }
    g_s[n * CINCH + c] = (a0 + a1 + a2 + a3) * DENSE_COEF + dense_b[c];
}

__global__ void k_w2(const float* __restrict__ conv_w) {
    const int i = blockIdx.x * 256 + threadIdx.x;
    float acc = 0.0f;
#pragma unroll
    for (int t = 0; t < 9; ++t) {
        float v = conv_w[t * (CINCH * COUTC) + i];
        acc = fmaf(v, v, acc);
    }
    g_w2[i] = acc * CONV_COEF2;
}

__global__ void k_demod() {
    __shared__ float s2[CINCH];
    const int n = blockIdx.x;
    const int c = threadIdx.x;
    float sv = g_s[n * CINCH + c];
    s2[c] = sv * sv;
    __syncthreads();
    float acc = 0.0f;
#pragma unroll 8
    for (int ci = 0; ci < CINCH; ++ci)
        acc = fmaf(s2[ci], g_w2[ci * COUTC + c], acc);
    g_d[n * COUTC + c] = rsqrtf(acc + 1e-8f);
}

// ---------------------------------------------------------------------------
// Weight transform: U[pos][cout][cin] = (G (w*coef) G^T)[pos], fp16
// ---------------------------------------------------------------------------
__global__ void k_wino_u(const float* __restrict__ conv_w) {
    __shared__ float tw[9][32][33];
    const int ci0 = blockIdx.x * 32;
    const int co0 = blockIdx.y * 32;
    const int tx = threadIdx.x;   // 0..31
    const int ty = threadIdx.y;   // 0..7
#pragma unroll
    for (int t = 0; t < 9; ++t)
#pragma unroll
        for (int i = 0; i < 4; ++i) {
            const int ci = ty + i * 8;
            tw[t][ci][tx] = conv_w[((size_t)t * CINCH + ci0 + ci) * COUTC + co0 + tx];
        }
    __syncthreads();
#pragma unroll
    for (int i = 0; i < 4; ++i) {
        const int co_l = ty + i * 8;
        float g[3][3];
#pragma unroll
        for (int k = 0; k < 9; ++k)
            g[k / 3][k % 3] = tw[k][tx][co_l] * CONV_COEF;
        float tg[4][3];
#pragma unroll
        for (int c = 0; c < 3; ++c) {
            tg[0][c] = g[0][c];
            tg[1][c] = 0.5f * (g[0][c] + g[1][c] + g[2][c]);
            tg[2][c] = 0.5f * (g[0][c] - g[1][c] + g[2][c]);
            tg[3][c] = g[2][c];
        }
        const size_t b = (size_t)(co0 + co_l) * CINCH + ci0 + tx;
#pragma unroll
        for (int r = 0; r < 4; ++r) {
            const float u0 = tg[r][0];
            const float u1 = 0.5f * (tg[r][0] + tg[r][1] + tg[r][2]);
            const float u2 = 0.5f * (tg[r][0] - tg[r][1] + tg[r][2]);
            const float u3 = tg[r][2];
            g_U[(size_t)(r * 4 + 0) * (CINCH * COUTC) + b] = __float2half_rn(u0);
            g_U[(size_t)(r * 4 + 1) * (CINCH * COUTC) + b] = __float2half_rn(u1);
            g_U[(size_t)(r * 4 + 2) * (CINCH * COUTC) + b] = __float2half_rn(u2);
            g_U[(size_t)(r * 4 + 3) * (CINCH * COUTC) + b] = __float2half_rn(u3);
        }
    }
}

// ---------------------------------------------------------------------------
// Input transform fused with modulation: V[pos][p][cin] = B^T (x*s) B, fp16
// grid = 8192, block = 256 (2 consecutive cin per thread, half2 stores)
// ---------------------------------------------------------------------------
__global__ void k_wino_v(const float* __restrict__ data) {
    const int p  = blockIdx.x;
    const int ci = threadIdx.x * 2;
    const int n  = p >> 10;
    const int ty = (p >> 5) & 31;
    const int tx = p & 31;
    const int y0 = 2 * ty - 1;
    const int x0 = 2 * tx - 1;
    const float2 sv = *(const float2*)(g_s + n * CINCH + ci);

    float2 d[4][4];
#pragma unroll
    for (int r = 0; r < 4; ++r) {
        const int h = y0 + r;
        const bool hv = (unsigned)h < 64u;
#pragma unroll
        for (int c = 0; c < 4; ++c) {
            const int w = x0 + c;
            float2 v = make_float2(0.f, 0.f);
            if (hv && (unsigned)w < 64u) {
                const float2 x = *(const float2*)(
                    data + ((size_t)((n * 64 + h) * 64 + w)) * CINCH + ci);
                v.x = x.x * sv.x;
                v.y = x.y * sv.y;
            }
            d[r][c] = v;
        }
    }
    float2 t[4][4];
#pragma unroll
    for (int c = 0; c < 4; ++c) {
        t[0][c] = make_float2(d[0][c].x - d[2][c].x, d[0][c].y - d[2][c].y);
        t[1][c] = make_float2(d[1][c].x + d[2][c].x, d[1][c].y + d[2][c].y);
        t[2][c] = make_float2(d[2][c].x - d[1][c].x, d[2][c].y - d[1][c].y);
        t[3][c] = make_float2(d[1][c].x - d[3][c].x, d[1][c].y - d[3][c].y);
    }
    const size_t pb = (size_t)p * CINCH + ci;
    const size_t ps = (size_t)P_TILES * CINCH;
#pragma unroll
    for (int r = 0; r < 4; ++r) {
        float2 v0 = make_float2(t[r][0].x - t[r][2].x, t[r][0].y - t[r][2].y);
        float2 v1 = make_float2(t[r][1].x + t[r][2].x, t[r][1].y + t[r][2].y);
        float2 v2 = make_float2(t[r][2].x - t[r][1].x, t[r][2].y - t[r][1].y);
        float2 v3 = make_float2(t[r][1].x - t[r][3].x, t[r][1].y - t[r][3].y);
        *(__half2*)(g_V + (size_t)(r * 4 + 0) * ps + pb) = __floats2half2_rn(v0.x, v0.y);
        *(__half2*)(g_V + (size_t)(r * 4 + 1) * ps + pb) = __floats2half2_rn(v1.x, v1.y);
        *(__half2*)(g_V + (size_t)(r * 4 + 2) * ps + pb) = __floats2half2_rn(v2.x, v2.y);
        *(__half2*)(g_V + (size_t)(r * 4 + 3) * ps + pb) = __floats2half2_rn(v3.x, v3.y);
    }
}

// ---------------------------------------------------------------------------
// Staging for the Winograd-domain GEMM
// ---------------------------------------------------------------------------
__device__ __forceinline__ void stage_load(uint32_t sA, uint32_t sB, int s,
                                           int tid, int pos, int bm, int bn) {
    const int ci0 = s * BK;
    const __half* va = g_V + (size_t)pos * (P_TILES * CINCH);
    const __half* ub = g_U + (size_t)pos * (CINCH * COUTC);
#pragma unroll
    for (int i = 0; i < 2; ++i) {
        const int c  = tid + 256 * i;
        const int m  = c >> 2;
        const int ch = c & 3;
        cpa16(sA + m * ROWB + ch * 16,
              va + (size_t)(bm + m) * CINCH + ci0 + ch * 8);
    }
#pragma unroll
    for (int i = 0; i < 2; ++i) {
        const int c  = tid + 256 * i;
        const int nn = c >> 2;
        const int ch = c & 3;
        cpa16(sB + nn * ROWB + ch * 16,
              ub + (size_t)(bn + nn) * CINCH + ci0 + ch * 8);
    }
}

// ---------------------------------------------------------------------------
// Winograd-domain GEMM: 16 x [8192 x 512 x 512], persistent fp16 mma.sync
// grid = 304, block = 256, tile 128x128; M written as fp16 (half2 stores)
// ---------------------------------------------------------------------------
__global__ void __launch_bounds__(256, 2)
k_wino_gemm() {
    extern __shared__ char sm[];
    __shared__ int s_tile;
    const uint32_t sbase = smem_u32(sm);

    const int tid  = threadIdx.x;
    const int wid  = tid >> 5;
    const int lane = tid & 31;
    const int gid  = lane >> 2;
    const int tid4 = lane & 3;
    const int l15  = lane & 15;
    const int lhi  = (lane >> 4) & 1;
    const int wm = (wid >> 2) * 64;
    const int wn = (wid & 3) * 32;

    uint32_t sA[STAGES], sB[STAGES];
#pragma unroll
    for (int st = 0; st < STAGES; ++st) {
        sA[st] = sbase + st * STAGE_BYTES;
        sB[st] = sA[st] + A_ST_BYTES;
    }
    const uint32_t a_off = (uint32_t)(wm + l15) * ROWB + lhi * 16;
    const uint32_t b_off = (uint32_t)(wn + l15) * ROWB + lhi * 16;

    for (;;) {
        CP_WAIT0();
        __syncthreads();
        if (tid == 0) s_tile = atomicAdd(&g_ctr, 1);
        __syncthreads();
        const int t = s_tile;
        if (t >= NTILES_G) break;

        const int bn  = (t & 3) * BN;
        const int bm  = ((t >> 2) & 63) * BM;
        const int pos = t >> 8;

        float acc[4][4][4];
#pragma unroll
        for (int i = 0; i < 4; ++i)
#pragma unroll
            for (int j = 0; j < 4; ++j)
#pragma unroll
                for (int r = 0; r < 4; ++r) acc[i][j][r] = 0.0f;

        stage_load(sA[0], sB[0], 0, tid, pos, bm, bn);
        CP_COMMIT();
        stage_load(sA[1], sB[1], 1, tid, pos, bm, bn);
        CP_COMMIT();
        stage_load(sA[2], sB[2], 2, tid, pos, bm, bn);
        CP_COMMIT();

        int buf = 0, nbuf = 3;
        for (int s = 0; s < NSTG; ++s) {
            CP_WAIT2();
            __syncthreads();

            if (s + 3 < NSTG)
                stage_load(sA[nbuf], sB[nbuf], s + 3, tid, pos, bm, bn);
            CP_COMMIT();

            const uint32_t Ab = sA[buf] + a_off;
            const uint32_t Bb = sB[buf] + b_off;

#pragma unroll
            for (int kk = 0; kk < 2; ++kk) {
                uint32_t a[4][4];
#pragma unroll
                for (int i = 0; i < 4; ++i)
                    LDMX4(a[i], Ab + i * (16 * ROWB) + kk * 32);
                uint32_t b[2][4];
#pragma unroll
                for (int j2 = 0; j2 < 2; ++j2)
                    LDMX4(b[j2], Bb + j2 * (16 * ROWB) + kk * 32);

#pragma unroll
                for (int i = 0; i < 4; ++i)
#pragma unroll
                    for (int j = 0; j < 4; ++j) {
                        const int j2 = j >> 1, od = j & 1;
                        MMA_F16(acc[i][j], a[i], b[j2][od], b[j2][2 + od]);
                    }
            }

            buf  = (buf == STAGES - 1) ? 0 : buf + 1;
            nbuf = (nbuf == STAGES - 1) ? 0 : nbuf + 1;
        }

        // write M (fp16, packed half2: acc quads hold two consecutive cols)
        __half* mb = g_M + (size_t)pos * (P_TILES * COUTC);
#pragma unroll
        for (int j = 0; j < 4; ++j) {
            const int col = bn + wn + j * 8 + 2 * tid4;
#pragma unroll
            for (int i = 0; i < 4; ++i) {
                const int r0 = bm + wm + i * 16 + gid;
#pragma unroll
                for (int half = 0; half < 2; ++half) {
                    const int rr = r0 + half * 8;
                    *(__half2*)(mb + (size_t)rr * COUTC + col) =
                        __floats2half2_rn(acc[i][j][half * 2 + 0],
                                          acc[i][j][half * 2 + 1]);
                }
            }
        }
    }
}

// ---------------------------------------------------------------------------
// Inverse transform + fused epilogue (demod, bias, noise, leaky)
// grid = 8192, block = 256 (2 consecutive couts per thread, half2 loads)
// ---------------------------------------------------------------------------
__global__ void k_wino_out(const float* __restrict__ bias,
                           const float* __restrict__ ncoef,
                           const float* __restrict__ noise,
                           float* __restrict__ out) {
    const int p  = blockIdx.x;
    const int co = threadIdx.x * 2;
    const int n  = p >> 10;
    const int ty = (p >> 5) & 31;
    const int tx = p & 31;

    float2 m[4][4];
    const size_t pb = (size_t)p * COUTC + co;
    const size_t ps = (size_t)P_TILES * COUTC;
#pragma unroll
    for (int pos = 0; pos < 16; ++pos)
        m[pos >> 2][pos & 3] = __half22float2(*(const __half2*)(g_M + (size_t)pos * ps + pb));

    float2 t0[4], t1[4];
#pragma unroll
    for (int c = 0; c < 4; ++c) {
        t0[c] = make_float2(m[0][c].x + m[1][c].x + m[2][c].x,
                            m[0][c].y + m[1][c].y + m[2][c].y);
        t1[c] = make_float2(m[1][c].x - m[2][c].x - m[3][c].x,
                            m[1][c].y - m[2][c].y - m[3][c].y);
    }
    float2 y[2][2];
    y[0][0] = make_float2(t0[0].x + t0[1].x + t0[2].x, t0[0].y + t0[1].y + t0[2].y);
    y[0][1] = make_float2(t0[1].x - t0[2].x - t0[3].x, t0[1].y - t0[2].y - t0[3].y);
    y[1][0] = make_float2(t1[0].x + t1[1].x + t1[2].x, t1[0].y + t1[1].y + t1[2].y);
    y[1][1] = make_float2(t1[1].x - t1[2].x - t1[3].x, t1[1].y - t1[2].y - t1[3].y);

    const float2 dv = *(const float2*)(g_d + n * COUTC + co);
    const float2 bv = *(const float2*)(bias + co);
    const float2 cv = *(const float2*)(ncoef + co);
#pragma unroll
    for (int r = 0; r < 2; ++r)
#pragma unroll
        for (int c = 0; c < 2; ++c) {
            const int h = 2 * ty + r;
            const int w = 2 * tx + c;
            const size_t idx = ((size_t)((n * 64 + h) * 64 + w)) * COUTC + co;
            const float2 nz = *(const float2*)(noise + idx);
            float2 o;
            o.x = fmaf(y[r][c].x, dv.x, fmaf(nz.x, cv.x, bv.x));
            o.y = fmaf(y[r][c].y, dv.y, fmaf(nz.y, cv.y, bv.y));
            o.x = (o.x >= 0.f) ? o.x : 0.2f * o.x;
            o.y = (o.y >= 0.f) ? o.y : 0.2f * o.y;
            *(float2*)(out + idx) = o;
        }
}

// ---------------------------------------------------------------------------
// Launch
// ---------------------------------------------------------------------------
extern "C" void kernel_launch(void* const* d_in, const int* in_sizes, int n_in,
                              void* d_out, int out_size) {
    const float* data    = (const float*)d_in[0];
    const float* latent  = (const float*)d_in[1];
    const float* dense_w = (const float*)d_in[2];
    const float* dense_b = (const float*)d_in[3];
    const float* conv_w  = (const float*)d_in[4];
    const float* bias    = (const float*)d_in[5];
    const float* ncoef   = (const float*)d_in[6];
    const float* noise   = (const float*)d_in[7];
    float* out = (float*)d_out;

    static bool attr_set = false;
    if (!attr_set) {
        cudaFuncSetAttribute(k_wino_gemm, cudaFuncAttributeMaxDynamicSharedMemorySize,
                             SMEM_TOTAL);
        attr_set = true;
    }

    k_style<<<NB, CINCH>>>(latent, dense_w, dense_b);
    k_w2<<<(CINCH * COUTC) / 256, 256>>>(conv_w);
    k_demod<<<NB, COUTC>>>();
    k_wino_u<<<dim3(CINCH / 32, COUTC / 32), dim3(32, 8)>>>(conv_w);
    k_wino_v<<<P_TILES, 256>>>(data);
    k_wino_gemm<<<GRID_P, 256, SMEM_TOTAL>>>();
    k_wino_out<<<P_TILES, 256>>>(bias, ncoef, noise, out);
}